// round 2
// baseline (speedup 1.0000x reference)
#include <cuda_runtime.h>

// VanillaRNN fused persistent kernel.
// B=1024, T=512, I=64, H=128, O=10.
// Grid: 128 CTAs x 8 batch rows. Block: 256 threads.
// Thread (o, half): o = tid&127 output column, half = tid>>7 selects which
// 96 of the 192 concat-K (64 x-dims + 128 h-dims) this thread accumulates.
// W held in registers as packed f32x2 pairs along k; inputs broadcast from SMEM.

#define ROWS 8
#define NTHREADS 256
#define KTOT 192
#define KHALF 96
#define HDIM 128
#define IDIM 64
#define TSTEPS 512
#define ODIM 10

__device__ __forceinline__ unsigned long long ffma2(unsigned long long a,
                                                    unsigned long long b,
                                                    unsigned long long c) {
    unsigned long long d;
    asm("fma.rn.f32x2 %0, %1, %2, %3;" : "=l"(d) : "l"(a), "l"(b), "l"(c));
    return d;
}

__device__ __forceinline__ unsigned long long packf2(float lo, float hi) {
    return ((unsigned long long)__float_as_uint(hi) << 32) |
           (unsigned long long)__float_as_uint(lo);
}

__device__ __forceinline__ float sum2(unsigned long long a) {
    return __uint_as_float((unsigned)a) + __uint_as_float((unsigned)(a >> 32));
}

__global__ void __launch_bounds__(NTHREADS, 1)
rnn_fused_kernel(const float* __restrict__ x,
                 const float* __restrict__ W_hx,
                 const float* __restrict__ W_hh,
                 const float* __restrict__ b_hh,
                 const float* __restrict__ W_ph,
                 const float* __restrict__ b_ph,
                 float* __restrict__ out) {
    __shared__ __align__(16) float inbuf[ROWS][KTOT];   // [.][0:64)=x_t, [.][64:192)=h_t
    __shared__ float red[2][ROWS][HDIM];                // cross-half partial sums
    __shared__ float bsh[HDIM];

    const int tid  = threadIdx.x;
    const int o    = tid & 127;        // output column
    const int half = tid >> 7;         // k-half: 0 -> k[0:96), 1 -> k[96:192)
    const int kbase = half * KHALF;
    const int b0   = blockIdx.x * ROWS;

    // ---- Load this thread's W column-slice into registers, packed pairwise along k.
    // concatK layout: k<64 -> W_hx[o][k]; k>=64 -> W_hh[o][k-64].
    unsigned long long wreg[KHALF / 2];
#pragma unroll
    for (int i = 0; i < KHALF / 2; i++) {
        const int k0 = kbase + 2 * i;
        const int k1 = k0 + 1;
        const float w0 = (k0 < IDIM) ? W_hx[o * IDIM + k0] : W_hh[o * HDIM + (k0 - IDIM)];
        const float w1 = (k1 < IDIM) ? W_hx[o * IDIM + k1] : W_hh[o * HDIM + (k1 - IDIM)];
        wreg[i] = packf2(w0, w1);
    }

    if (half == 0) bsh[o] = b_hh[o];

    // h0 = 0
#pragma unroll
    for (int mm = 0; mm < 4; mm++) {
        inbuf[half * 4 + mm][IDIM + o] = 0.0f;
    }

    // x loading: warp w owns batch row w; lane l loads a float2.
    const int w = tid >> 5;
    const int l = tid & 31;
    const float* xrow = x + (size_t)(b0 + w) * TSTEPS * IDIM;
    ((float2*)&inbuf[w][0])[l] = *(const float2*)(xrow + 2 * l);  // t = 0

    __syncthreads();

    for (int t = 0; t < TSTEPS; t++) {
        // Prefetch x for t+1 into registers (consumed ~1500 cyc later).
        float2 xnext;
        if (t + 1 < TSTEPS) xnext = *(const float2*)(xrow + (size_t)(t + 1) * IDIM + 2 * l);

        // ---- main accumulation: acc over this thread's 96 k's for all 8 rows.
        float accs[ROWS];
#pragma unroll
        for (int m = 0; m < ROWS; m++) {
            unsigned long long a0 = 0ull, a1 = 0ull;  // two chains for ILP
            const ulonglong2* p = (const ulonglong2*)&inbuf[m][kbase];
#pragma unroll
            for (int i = 0; i < 24; i += 2) {
                ulonglong2 v0 = p[i];
                ulonglong2 v1 = p[i + 1];
                a0 = ffma2(v0.x, wreg[2 * i + 0], a0);
                a1 = ffma2(v0.y, wreg[2 * i + 1], a1);
                a0 = ffma2(v1.x, wreg[2 * i + 2], a0);
                a1 = ffma2(v1.y, wreg[2 * i + 3], a1);
            }
            accs[m] = sum2(a0) + sum2(a1);
        }

        // ---- cross-half reduction (red untouched by compute; all inbuf reads
        // are complete once every thread reaches the barrier below).
#pragma unroll
        for (int m = 0; m < ROWS; m++) red[half][m][o] = accs[m];
        __syncthreads();

        // half 0 finalizes rows 0..3, half 1 rows 4..7.
#pragma unroll
        for (int mm = 0; mm < 4; mm++) {
            const int m = half * 4 + mm;
            const float z = red[0][m][o] + red[1][m][o] + bsh[o];
            inbuf[m][IDIM + o] = tanhf(z);
        }
        if (t + 1 < TSTEPS) ((float2*)&inbuf[w][0])[l] = xnext;
        __syncthreads();
    }

    // ---- final projection: out[b0+m][j] = b_ph[j] + sum_k h[m][k] * W_ph[j][k]
    if (tid < ROWS * ODIM) {
        const int m = tid / ODIM;
        const int j = tid % ODIM;
        float s = b_ph[j];
#pragma unroll 4
        for (int k = 0; k < HDIM; k++) {
            s += inbuf[m][IDIM + k] * W_ph[j * HDIM + k];
        }
        out[(size_t)(b0 + m) * ODIM + j] = s;
    }
}

extern "C" void kernel_launch(void* const* d_in, const int* in_sizes, int n_in,
                              void* d_out, int out_size) {
    const float* x    = (const float*)d_in[0];
    const float* W_hx = (const float*)d_in[1];
    const float* W_hh = (const float*)d_in[2];
    const float* b_hh = (const float*)d_in[3];
    const float* W_ph = (const float*)d_in[4];
    const float* b_ph = (const float*)d_in[5];
    float* out = (float*)d_out;

    rnn_fused_kernel<<<1024 / ROWS, NTHREADS>>>(x, W_hx, W_hh, b_hh, W_ph, b_ph, out);
}

// round 3
// speedup vs baseline: 1.0855x; 1.0855x over previous
#include <cuda_runtime.h>

// VanillaRNN fused persistent kernel, v2.
// B=1024, T=512, I=64, H=128, O=10.
// Grid: 128 CTAs x 8 batch rows. Block: 256 threads (8 warps).
//
// Thread mapping: op = warp*8 + (lane>>2) in [0,64), seg = lane&3.
// Thread owns TWO output columns o0=op, o1=op+64 (halves LDS per FMA),
// and k-segment [seg*48, seg*48+48) of the 192-wide concat(x_t, h_t).
// Cross-segment reduction via __shfl_xor (1,2). Double-buffered smem state
// -> exactly ONE __syncthreads per timestep.
//
// Physical smem layout per row: 4 segments of 48 floats, each padded by 4
// floats (stride 52) so the 4 segment bases hit distinct bank groups
// (base%32 banks = 0,20,8,28). phys(k) = k + 4*(k/48).

#define ROWS 8
#define NTHREADS 256
#define HDIM 128
#define IDIM 64
#define TSTEPS 512
#define ODIM 10
#define SEGF 48         // logical floats per segment
#define SEGP 52         // physical stride per segment
#define RSTRIDE 208     // 4*SEGP floats per row

__device__ __forceinline__ unsigned long long ffma2(unsigned long long a,
                                                    unsigned long long b,
                                                    unsigned long long c) {
    unsigned long long d;
    asm("fma.rn.f32x2 %0, %1, %2, %3;" : "=l"(d) : "l"(a), "l"(b), "l"(c));
    return d;
}

__device__ __forceinline__ unsigned long long packf2(float lo, float hi) {
    return ((unsigned long long)__float_as_uint(hi) << 32) |
           (unsigned long long)__float_as_uint(lo);
}

__device__ __forceinline__ float sum2(unsigned long long a) {
    return __uint_as_float((unsigned)a) + __uint_as_float((unsigned)(a >> 32));
}

__device__ __forceinline__ float fast_tanh(float z) {
    // tanh(z) = 1 - 2/(exp(2z)+1); MUFU-based, ~1e-6 abs error.
    float e = __expf(2.0f * z);
    return 1.0f - __fdividef(2.0f, e + 1.0f);
}

__device__ __forceinline__ int physk(int k) { return k + 4 * (k / SEGF); }

// weight fetch for concat-k: k<64 -> W_hx[o][k], else W_hh[o][k-64]
__device__ __forceinline__ float wpick(const float* __restrict__ W_hx,
                                       const float* __restrict__ W_hh,
                                       int o, int k) {
    return (k < IDIM) ? W_hx[o * IDIM + k] : W_hh[o * HDIM + (k - IDIM)];
}

__global__ void __launch_bounds__(NTHREADS, 1)
rnn_fused_kernel(const float* __restrict__ x,
                 const float* __restrict__ W_hx,
                 const float* __restrict__ W_hh,
                 const float* __restrict__ b_hh,
                 const float* __restrict__ W_ph,
                 const float* __restrict__ b_ph,
                 float* __restrict__ out) {
    __shared__ __align__(16) float buf[2][ROWS][RSTRIDE];

    const int tid  = threadIdx.x;
    const int lane = tid & 31;
    const int warp = tid >> 5;
    const int seg  = lane & 3;            // k-segment 0..3
    const int op   = warp * 8 + (lane >> 2);  // 0..63
    const int o0   = op;
    const int o1   = op + 64;
    const int b0r  = blockIdx.x * ROWS;
    const int kb   = seg * SEGF;          // logical k base

    // ---- weights: 24 packed f32x2 per output column (48 logical k each)
    unsigned long long w0[24], w1[24];
#pragma unroll
    for (int j = 0; j < 24; j++) {
        const int k0 = kb + 2 * j, k1 = k0 + 1;
        w0[j] = packf2(wpick(W_hx, W_hh, o0, k0), wpick(W_hx, W_hh, o0, k1));
        w1[j] = packf2(wpick(W_hx, W_hh, o1, k0), wpick(W_hx, W_hh, o1, k1));
    }
    const float bb0 = b_hh[o0];
    const float bb1 = b_hh[o1];
    const int ph0 = physk(IDIM + o0);     // smem col of h[o0]
    const int ph1 = physk(IDIM + o1);     // smem col of h[o1]
    const int m0 = 2 * seg;               // rows this lane finalizes
    const int m1 = m0 + 1;

    // ---- zero both buffers (h0 = 0, pads whatever)
    for (int i = tid; i < 2 * ROWS * RSTRIDE; i += NTHREADS)
        ((float*)buf)[i] = 0.0f;

    // ---- x loader mapping: tid<128, row r, 4-float chunk c4
    const int xr  = tid >> 4;             // 0..7
    const int c4  = (tid & 15) * 4;       // 0..60
    const int pc4 = (c4 < SEGF) ? c4 : c4 + 4;  // physical col (never straddles)
    const float* xrow = x + (size_t)(b0r + xr) * TSTEPS * IDIM;

    if (tid < 128) {
        float4 v = *(const float4*)(xrow + c4);   // t = 0
        *(float4*)&buf[0][xr][pc4] = v;
    }
    __syncthreads();

    int p = 0;
    for (int t = 0; t < TSTEPS; t++) {
        // prefetch x_{t+1} into registers (hidden under the FMA block)
        float4 xn;
        if (tid < 128) {
            const int tn = (t + 1 < TSTEPS) ? t + 1 : TSTEPS - 1;
            xn = *(const float4*)(xrow + (size_t)tn * IDIM + c4);
        }

        // ---- accumulate: 8 rows x 2 output cols over this thread's 48 k's
        float s0[ROWS], s1[ROWS];
#pragma unroll
        for (int m = 0; m < ROWS; m++) {
            const ulonglong2* pp =
                (const ulonglong2*)&buf[p][m][seg * SEGP];
            unsigned long long a00 = 0ull, a01 = 0ull, a10 = 0ull, a11 = 0ull;
#pragma unroll
            for (int i = 0; i < 12; i++) {
                ulonglong2 v = pp[i];
                a00 = ffma2(v.x, w0[2 * i + 0], a00);
                a01 = ffma2(v.y, w0[2 * i + 1], a01);
                a10 = ffma2(v.x, w1[2 * i + 0], a10);
                a11 = ffma2(v.y, w1[2 * i + 1], a11);
            }
            s0[m] = sum2(a00) + sum2(a01);
            s1[m] = sum2(a10) + sum2(a11);
        }

        // ---- cross-segment reduction (4 lanes share each (op,row))
#pragma unroll
        for (int m = 0; m < ROWS; m++) {
            s0[m] += __shfl_xor_sync(0xffffffffu, s0[m], 1);
            s0[m] += __shfl_xor_sync(0xffffffffu, s0[m], 2);
            s1[m] += __shfl_xor_sync(0xffffffffu, s1[m], 1);
            s1[m] += __shfl_xor_sync(0xffffffffu, s1[m], 2);
        }

        // lane (seg) finalizes rows m0, m1 for its two columns
        float v00, v01, v10, v11;
#pragma unroll
        for (int m = 0; m < ROWS; m += 2) {
            if (seg == (m >> 1)) {
                v00 = s0[m]; v01 = s0[m + 1];
                v10 = s1[m]; v11 = s1[m + 1];
            }
        }

        const int q = p ^ 1;
        buf[q][m0][ph0] = fast_tanh(v00 + bb0);
        buf[q][m1][ph0] = fast_tanh(v01 + bb0);
        buf[q][m0][ph1] = fast_tanh(v10 + bb1);
        buf[q][m1][ph1] = fast_tanh(v11 + bb1);

        if (tid < 128) *(float4*)&buf[q][xr][pc4] = xn;

        __syncthreads();
        p = q;
    }

    // ---- final projection: out[b0r+m][j] = b_ph[j] + sum_k h[m][k]*W_ph[j][k]
    if (tid < ROWS * ODIM) {
        const int m = tid / ODIM;
        const int j = tid % ODIM;
        float s = b_ph[j];
#pragma unroll 4
        for (int k = 0; k < HDIM; k++) {
            s += buf[p][m][physk(IDIM + k)] * W_ph[j * HDIM + k];
        }
        out[(size_t)(b0r + m) * ODIM + j] = s;
    }
}

extern "C" void kernel_launch(void* const* d_in, const int* in_sizes, int n_in,
                              void* d_out, int out_size) {
    const float* x    = (const float*)d_in[0];
    const float* W_hx = (const float*)d_in[1];
    const float* W_hh = (const float*)d_in[2];
    const float* b_hh = (const float*)d_in[3];
    const float* W_ph = (const float*)d_in[4];
    const float* b_ph = (const float*)d_in[5];
    float* out = (float*)d_out;

    rnn_fused_kernel<<<1024 / ROWS, NTHREADS>>>(x, W_hx, W_hh, b_hh, W_ph, b_ph, out);
}

// round 4
// speedup vs baseline: 1.4239x; 1.3117x over previous
#include <cuda_runtime.h>

// VanillaRNN fused persistent kernel, v3.
// B=1024, T=512, I=64, H=128, O=10.
// Grid: 128 CTAs x 8 batch rows. Block: 256 threads (8 warps).
//
// Thread mapping: g = warp*4 + (lane&3) in [0,32): column group.
//                 seg = lane>>2 in [0,8): k-segment [seg*24, seg*24+24).
// Thread owns FOUR output columns {g, g+32, g+64, g+96} (4 MACs per loaded
// input float -> halves smem-requested bytes vs v2) and one 24-wide k-segment
// of the 192-wide concat(x_t, h_t).
//
// Cross-segment reduction: 3-stage butterfly TREE exchange (xor 4, 8, 16)
// that halves the live row set each stage -> 28 shuffles/thread (not 96).
// After stage 3, lane owns row bitrev3(seg) fully reduced for its 4 cols.
//
// Double-buffered smem state -> ONE __syncthreads per timestep.
// Physical layout per row: 8 segments of 24 floats padded to stride 28
// (bases distinct mod 32 banks); row stride 228 floats (!= 0 mod 32).

#define ROWS 8
#define NTHREADS 256
#define HDIM 128
#define IDIM 64
#define TSTEPS 512
#define ODIM 10
#define SEGF 24
#define SEGP 28
#define RSTRIDE 228

__device__ __forceinline__ unsigned long long ffma2(unsigned long long a,
                                                    unsigned long long b,
                                                    unsigned long long c) {
    unsigned long long d;
    asm("fma.rn.f32x2 %0, %1, %2, %3;" : "=l"(d) : "l"(a), "l"(b), "l"(c));
    return d;
}

__device__ __forceinline__ unsigned long long packf2(float lo, float hi) {
    return ((unsigned long long)__float_as_uint(hi) << 32) |
           (unsigned long long)__float_as_uint(lo);
}

__device__ __forceinline__ float sum2(unsigned long long a) {
    return __uint_as_float((unsigned)a) + __uint_as_float((unsigned)(a >> 32));
}

__device__ __forceinline__ float fast_tanh(float z) {
    float e = __expf(2.0f * z);
    return 1.0f - __fdividef(2.0f, e + 1.0f);
}

__device__ __forceinline__ int physk(int k) { return k + 4 * (k / SEGF); }

__device__ __forceinline__ float wpick(const float* __restrict__ W_hx,
                                       const float* __restrict__ W_hh,
                                       int o, int k) {
    return (k < IDIM) ? W_hx[o * IDIM + k] : W_hh[o * HDIM + (k - IDIM)];
}

__global__ void __launch_bounds__(NTHREADS, 1)
rnn_fused_kernel(const float* __restrict__ x,
                 const float* __restrict__ W_hx,
                 const float* __restrict__ W_hh,
                 const float* __restrict__ b_hh,
                 const float* __restrict__ W_ph,
                 const float* __restrict__ b_ph,
                 float* __restrict__ out) {
    __shared__ __align__(16) float buf[2][ROWS][RSTRIDE];

    const int tid  = threadIdx.x;
    const int lane = tid & 31;
    const int warp = tid >> 5;
    const int g    = warp * 4 + (lane & 3);   // col group 0..31
    const int seg  = lane >> 2;               // k-segment 0..7
    const int kb   = seg * SEGF;
    const int b0r  = blockIdx.x * ROWS;

    // ---- weights: 4 cols x 12 packed f32x2 (24 logical k per col)
    unsigned long long w[4][12];
    float bb[4];
#pragma unroll
    for (int c = 0; c < 4; c++) {
        const int o = g + 32 * c;
#pragma unroll
        for (int j = 0; j < 12; j++) {
            const int k0 = kb + 2 * j;
            w[c][j] = packf2(wpick(W_hx, W_hh, o, k0),
                             wpick(W_hx, W_hh, o, k0 + 1));
        }
        bb[c] = b_hh[o];
    }

    // row this lane finalizes after the tree reduction: bitrev3(seg)
    const int mstar = 4 * (seg & 1) + 2 * ((seg >> 1) & 1) + ((seg >> 2) & 1);
    int phcol[4];
#pragma unroll
    for (int c = 0; c < 4; c++) phcol[c] = physk(IDIM + g + 32 * c);

    // ---- zero both buffers (h0 = 0, pads don't matter)
    for (int i = tid; i < 2 * ROWS * RSTRIDE; i += NTHREADS)
        ((float*)buf)[i] = 0.0f;

    // ---- x loader: tid<128, row xr, 4-float chunk c4 (never straddles a segment)
    const int xr  = tid >> 4;
    const int c4  = (tid & 15) * 4;
    const int pc4 = c4 + 4 * (c4 / SEGF);
    const float* xrow = x + (size_t)(b0r + xr) * TSTEPS * IDIM;

    if (tid < 128) {
        float4 v = *(const float4*)(xrow + c4);
        *(float4*)&buf[0][xr][pc4] = v;
    }
    __syncthreads();

    int p = 0;
    for (int t = 0; t < TSTEPS; t++) {
        // prefetch x_{t+1}
        float4 xn;
        if (tid < 128) {
            const int tn = (t + 1 < TSTEPS) ? t + 1 : TSTEPS - 1;
            xn = *(const float4*)(xrow + (size_t)tn * IDIM + c4);
        }

        // ---- accumulate: 8 rows x 4 cols over this thread's 24 k's
        float s[ROWS][4];
#pragma unroll
        for (int m = 0; m < ROWS; m++) {
            const ulonglong2* pp = (const ulonglong2*)&buf[p][m][seg * SEGP];
            unsigned long long a0 = 0ull, a1 = 0ull, a2 = 0ull, a3 = 0ull;
#pragma unroll
            for (int i = 0; i < 6; i++) {
                ulonglong2 v = pp[i];
                a0 = ffma2(v.x, w[0][2 * i], a0);
                a1 = ffma2(v.x, w[1][2 * i], a1);
                a2 = ffma2(v.x, w[2][2 * i], a2);
                a3 = ffma2(v.x, w[3][2 * i], a3);
                a0 = ffma2(v.y, w[0][2 * i + 1], a0);
                a1 = ffma2(v.y, w[1][2 * i + 1], a1);
                a2 = ffma2(v.y, w[2][2 * i + 1], a2);
                a3 = ffma2(v.y, w[3][2 * i + 1], a3);
            }
            s[m][0] = sum2(a0); s[m][1] = sum2(a1);
            s[m][2] = sum2(a2); s[m][3] = sum2(a3);
        }

        // ---- butterfly tree reduction over 8 segments (seg bits = lane bits 2..4)
        // stage 0: xor 4, split rows on {0-3 | 4-7}
        float r1[4][4];
        {
            const bool low = ((seg & 1) == 0);
#pragma unroll
            for (int r = 0; r < 4; r++)
#pragma unroll
                for (int c = 0; c < 4; c++) {
                    float send = low ? s[r + 4][c] : s[r][c];
                    float recv = __shfl_xor_sync(0xffffffffu, send, 4);
                    float keep = low ? s[r][c] : s[r + 4][c];
                    r1[r][c] = keep + recv;
                }
        }
        // stage 1: xor 8, split on {0-1 | 2-3}
        float r2[2][4];
        {
            const bool low = (((seg >> 1) & 1) == 0);
#pragma unroll
            for (int r = 0; r < 2; r++)
#pragma unroll
                for (int c = 0; c < 4; c++) {
                    float send = low ? r1[r + 2][c] : r1[r][c];
                    float recv = __shfl_xor_sync(0xffffffffu, send, 8);
                    float keep = low ? r1[r][c] : r1[r + 2][c];
                    r2[r][c] = keep + recv;
                }
        }
        // stage 2: xor 16, split on {0 | 1}
        float f[4];
        {
            const bool low = (((seg >> 2) & 1) == 0);
#pragma unroll
            for (int c = 0; c < 4; c++) {
                float send = low ? r2[1][c] : r2[0][c];
                float recv = __shfl_xor_sync(0xffffffffu, send, 16);
                float keep = low ? r2[0][c] : r2[1][c];
                f[c] = keep + recv;
            }
        }

        // ---- lane finalizes row mstar, its 4 cols
        const int q = p ^ 1;
#pragma unroll
        for (int c = 0; c < 4; c++)
            buf[q][mstar][phcol[c]] = fast_tanh(f[c] + bb[c]);

        if (tid < 128) *(float4*)&buf[q][xr][pc4] = xn;

        __syncthreads();
        p = q;
    }

    // ---- final projection
    if (tid < ROWS * ODIM) {
        const int m = tid / ODIM;
        const int j = tid % ODIM;
        float s = b_ph[j];
#pragma unroll 4
        for (int k = 0; k < HDIM; k++)
            s += buf[p][m][physk(IDIM + k)] * W_ph[j * HDIM + k];
        out[(size_t)(b0r + m) * ODIM + j] = s;
    }
}

extern "C" void kernel_launch(void* const* d_in, const int* in_sizes, int n_in,
                              void* d_out, int out_size) {
    const float* x    = (const float*)d_in[0];
    const float* W_hx = (const float*)d_in[1];
    const float* W_hh = (const float*)d_in[2];
    const float* b_hh = (const float*)d_in[3];
    const float* W_ph = (const float*)d_in[4];
    const float* b_ph = (const float*)d_in[5];
    float* out = (float*)d_out;

    rnn_fused_kernel<<<1024 / ROWS, NTHREADS>>>(x, W_hx, W_hh, b_hh, W_ph, b_ph, out);
}